// round 11
// baseline (speedup 1.0000x reference)
#include <cuda_runtime.h>
#include <cuda_bf16.h>

#define NRAYS 4096
#define NTETS 3072
#define NVERT 729
#define NFACE 12288
#define MAXS  128
#define MAXB  896          // boundary-tri capacity (actual count = 768)

// dynamic smem layout (bytes)
#define OFF_TRI   0
#define SZ_TRI    (MAXB * 3 * 16)          // 43008
#define OFF_TET   (OFF_TRI + SZ_TRI)       // 43008
#define SZ_TET    (NTETS * 16)             // 49152
#define OFF_VRT   (OFF_TET + SZ_TET)       // 92160
#define SZ_VRT    ((NVERT * 3 * 4 + 15) & ~15)  // 8752
#define OFF_KEY   (OFF_VRT + SZ_VRT)       // 100912
#define SZ_KEY    (32 * 8)                 // 256
#define OFF_NB    (OFF_KEY + SZ_KEY)       // 101168
#define SMEM_TOTAL (OFF_NB + 16)           // 101184

struct F3 { float x, y, z; };
__device__ __forceinline__ F3 mkf3(float x, float y, float z) { F3 r; r.x = x; r.y = y; r.z = z; return r; }
__device__ __forceinline__ F3 sub3(F3 a, F3 b) { return mkf3(a.x - b.x, a.y - b.y, a.z - b.z); }
__device__ __forceinline__ F3 cross3(F3 a, F3 b) {
    return mkf3(a.y * b.z - a.z * b.y,
                a.z * b.x - a.x * b.z,
                a.x * b.y - a.y * b.x);
}
__device__ __forceinline__ float dot3(F3 a, F3 b) { return a.x * b.x + a.y * b.y + a.z * b.z; }
__device__ __forceinline__ F3 ld3(const float* p) { return mkf3(p[0], p[1], p[2]); }

// ---------------- single fused kernel -----------------------------------------
// 128 blocks x 1024 threads (32 warps), 101KB dynamic smem, 1 block/SM.
// Phase 0: (a) coalesced copy of tetras (int4) + verts into smem;
//          (b) compact boundary tris (topo<0 <=> boundary; topo flattened is
//              indexed exactly by face id; first hit from outside a watertight
//              mesh is always a boundary face) into smem via block-local
//              atomic counter (order-independent min-reduction follows).
// Phase 1: isect — 32 rays x 32 tri-slices over smem tris; shared atomicMin on
//          packed (t_bits<<32 | fid) == first-occurrence argmin.
// Phase 2: march — warp w marches ray w: 32 lanes evaluate bary for 32
//          consecutive steps against the warp-uniform cached tet; ballot finds
//          the first non-inside step; earlier lanes emit directly; all lanes
//          redundantly run the verbatim R3 walk for the failing step (now with
//          smem tet/vert loads: same bits, ~4x lower hop latency); repeat.
__global__ void __launch_bounds__(1024) k_all(const float* __restrict__ verts,
                                              const float* __restrict__ ro,
                                              const float* __restrict__ rd,
                                              const int* __restrict__ tetras,
                                              const int* __restrict__ faces,
                                              const int* __restrict__ topo,
                                              float* __restrict__ out) {
    extern __shared__ unsigned char dynsmem[];
    float4* s_tri = (float4*)(dynsmem + OFF_TRI);
    int4*   s_tet = (int4*)(dynsmem + OFF_TET);
    float*  s_vrt = (float*)(dynsmem + OFF_VRT);
    unsigned long long* skey = (unsigned long long*)(dynsmem + OFF_KEY);
    int* s_nb = (int*)(dynsmem + OFF_NB);

    int tid  = threadIdx.x;
    int lane = tid & 31;
    int wid  = tid >> 5;                 // 0..31

    if (tid == 0) *s_nb = 0;
    if (tid < 32)
        skey[tid] = ((unsigned long long)__float_as_uint(1e10f) << 32); // (1e10, 0)
    __syncthreads();

    // ---------------- phase 0a: coalesced smem staging ----------------------
    for (int i = tid; i < NTETS; i += 1024)
        s_tet[i] = ((const int4*)tetras)[i];
    for (int i = tid; i < NVERT * 3; i += 1024)
        s_vrt[i] = verts[i];

    // ---------------- phase 0b: per-block boundary-tri compaction -----------
    for (int fid = tid; fid < NFACE; fid += 1024) {
        if (topo[fid] < 0) {
            int slot = atomicAdd(s_nb, 1);
            if (slot < MAXB) {
                int v0 = faces[3 * fid + 0];
                int v1 = faces[3 * fid + 1];
                int v2 = faces[3 * fid + 2];
                F3 p0 = ld3(verts + 3 * v0);
                F3 p1 = ld3(verts + 3 * v1);
                F3 p2 = ld3(verts + 3 * v2);
                s_tri[3 * slot + 0] = make_float4(p0.x, p0.y, p0.z, __int_as_float(fid));
                s_tri[3 * slot + 1] = make_float4(p1.x - p0.x, p1.y - p0.y, p1.z - p0.z, 0.0f);
                s_tri[3 * slot + 2] = make_float4(p2.x - p0.x, p2.y - p0.y, p2.z - p0.z, 0.0f);
            }
        }
    }
    __syncthreads();

    // ---------------- phase 1: intersect (ray = lane, slice = wid) -----------
    {
        int iray = blockIdx.x * 32 + lane;
        F3 o = ld3(ro + 3 * iray);
        F3 d = ld3(rd + 3 * iray);
        int nb = *s_nb;
        if (nb > MAXB) nb = MAXB;

        float tmin = 1e10f;
        int   fmin = 0x7fffffff;
        for (int s = wid; s < nb; s += 32) {
            float4 q0 = s_tri[3 * s + 0];
            float4 q1 = s_tri[3 * s + 1];
            float4 q2 = s_tri[3 * s + 2];
            F3 p0 = mkf3(q0.x, q0.y, q0.z);
            F3 e1 = mkf3(q1.x, q1.y, q1.z);
            F3 e2 = mkf3(q2.x, q2.y, q2.z);
            int fid = __float_as_int(q0.w);

            F3 h = cross3(d, e2);
            float a = dot3(e1, h);
            bool anz = fabsf(a) > 1e-9f;
            float f = 1.0f / (anz ? a : 1e-9f);
            F3 s3 = sub3(o, p0);
            float u = f * dot3(s3, h);
            F3 q = cross3(s3, e1);
            float v = f * dot3(d, q);
            float tt = f * dot3(e2, q);
            bool ok = anz && (u >= 0.0f) && (u <= 1.0f) && (v >= 0.0f) &&
                      (u + v <= 1.0f) && (tt > 1e-6f);
            if (ok && (tt < tmin || (tt == tmin && fid < fmin))) { tmin = tt; fmin = fid; }
        }
        if (tmin < 1e10f) {
            unsigned long long key =
                ((unsigned long long)__float_as_uint(tmin) << 32) | (unsigned)fmin;
            atomicMin(&skey[lane], key);
        }
    }
    __syncthreads();

    // ---------------- phase 2: march (warp = ray) -----------------------------
    int ray = blockIdx.x * 32 + wid;

    unsigned long long key = skey[wid];
    float tmin = __uint_as_float((unsigned)(key >> 32));
    int   fidx = (int)(key & 0xffffffffu);

    bool  hit = tmin < 5.0f;
    float t0  = hit ? tmin : 0.0f;
    F3 o = ld3(ro + 3 * ray);
    F3 d = ld3(rd + 3 * ray);
    F3 hp = mkf3(o.x + t0 * d.x, o.y + t0 * d.y, o.z + t0 * d.z);
    int  tet   = hit ? (fidx >> 2) : 0;
    bool alive = hit;

    float* o_ray = out;
    float* o_tet = out + (size_t)NRAYS * MAXS;
    float* o_bar = out + (size_t)2 * NRAYS * MAXS;
    float* o_ts  = out + (size_t)6 * NRAYS * MAXS;
    float* o_te  = o_ts + NRAYS;
    float* o_pos = o_te + NRAYS;

    if (lane == 0) {
        o_ts[ray] = t0;
        o_te[ray] = hit ? (t0 + 0.05f) : 0.0f;
    }

    const float STEPF = (float)(0.05 / 128.0);

    // warp-uniform register cache of the current tet (R3's exact arithmetic,
    // data now sourced from smem -- identical bits)
    F3 ca, ce1, ce2, ce3, cc23;
    float cinv = 0.0f;
    if (alive) {
        int4 tv = s_tet[tet];
        ca  = ld3(s_vrt + 3 * tv.x);
        F3 b  = ld3(s_vrt + 3 * tv.y);
        F3 c  = ld3(s_vrt + 3 * tv.z);
        F3 dd = ld3(s_vrt + 3 * tv.w);
        ce1 = sub3(b, ca);
        ce2 = sub3(c, ca);
        ce3 = sub3(dd, ca);
        cc23 = cross3(ce2, ce3);
        float det = dot3(ce1, cc23);
        cinv = 1.0f / det;
    }

    int k = 0;
    while (k < MAXS) {
        if (!alive) {
            for (int kk = k + lane; kk < MAXS; kk += 32) {
                int idx = ray * MAXS + kk;
                o_ray[idx] = -1.0f;
                o_tet[idx] = -1.0f;
                ((float4*)o_bar)[idx] = make_float4(0.f, 0.f, 0.f, 0.f);
                o_pos[3 * idx + 0] = 0.0f;
                o_pos[3 * idx + 1] = 0.0f;
                o_pos[3 * idx + 2] = 0.0f;
            }
            break;
        }

        int count = MAXS - k;
        if (count > 32) count = 32;

        // ---- speculative parallel bary for steps k..k+count-1 (tet T) ------
        float w0 = 0.f, w1 = 0.f, w2 = 0.f, w3 = 0.f;
        F3 p = mkf3(0.f, 0.f, 0.f);
        bool inside = false;
        if (lane < count) {
            float tk = (float)(k + lane) * STEPF + 1e-4f;
            p = mkf3(hp.x + tk * d.x, hp.y + tk * d.y, hp.z + tk * d.z);
            F3 r = sub3(p, ca);
            w1 = dot3(r, cc23) * cinv;
            F3 cr3 = cross3(r, ce3);
            w2 = dot3(ce1, cr3) * cinv;
            F3 c2r = cross3(ce2, r);
            w3 = dot3(ce1, c2r) * cinv;
            w0 = 1.0f - (w1 + w2 + w3);
            inside = (w0 >= -1e-6f) && (w1 >= -1e-6f) &&
                     (w2 >= -1e-6f) && (w3 >= -1e-6f);
        }
        unsigned bal = __ballot_sync(0xffffffffu, (lane < count) && !inside);
        int n_ok = (bal == 0u) ? count : (__ffs(bal) - 1);

        // ---- emit the n_ok proven-inside steps (lane-consecutive stores) ---
        if (lane < n_ok) {
            int idx = ray * MAXS + k + lane;
            o_ray[idx] = (float)ray;
            o_tet[idx] = (float)tet;
            ((float4*)o_bar)[idx] = make_float4(w0, w1, w2, w3);
            o_pos[3 * idx + 0] = p.x;
            o_pos[3 * idx + 1] = p.y;
            o_pos[3 * idx + 2] = p.z;
        }
        k += n_ok;
        if (bal == 0u) continue;

        // ---- failing step k: all lanes redundantly run the R3 walk ---------
        {
            float tk = (float)k * STEPF + 1e-4f;
            F3 pw = mkf3(hp.x + tk * d.x, hp.y + tk * d.y, hp.z + tk * d.z);
            float v0 = 0.f, v1 = 0.f, v2 = 0.f, v3 = 0.f;
            bool ins = false;
            bool moved_last = false;
            for (int it = 0; it < 3; ++it) {
                F3 r = sub3(pw, ca);
                v1 = dot3(r, cc23) * cinv;
                F3 cr3 = cross3(r, ce3);
                v2 = dot3(ce1, cr3) * cinv;
                F3 c2r = cross3(ce2, r);
                v3 = dot3(ce1, c2r) * cinv;
                v0 = 1.0f - (v1 + v2 + v3);
                ins = (v0 >= -1e-6f) && (v1 >= -1e-6f) &&
                      (v2 >= -1e-6f) && (v3 >= -1e-6f);
                moved_last = false;
                if (ins) break;
                int am = 0; float mv = v0;
                if (v1 < mv) { mv = v1; am = 1; }
                if (v2 < mv) { mv = v2; am = 2; }
                if (v3 < mv) { mv = v3; am = 3; }
                int nb = topo[4 * tet + (3 - am)];
                if (nb >= 0) {
                    tet = nb;
                    int4 tv = s_tet[tet];
                    ca  = ld3(s_vrt + 3 * tv.x);
                    F3 b  = ld3(s_vrt + 3 * tv.y);
                    F3 c  = ld3(s_vrt + 3 * tv.z);
                    F3 dd = ld3(s_vrt + 3 * tv.w);
                    ce1 = sub3(b, ca);
                    ce2 = sub3(c, ca);
                    ce3 = sub3(dd, ca);
                    cc23 = cross3(ce2, ce3);
                    float det = dot3(ce1, cc23);
                    cinv = 1.0f / det;
                    moved_last = true;
                } else { alive = false; break; }
            }
            if (alive && !ins && moved_last) {
                F3 r = sub3(pw, ca);
                v1 = dot3(r, cc23) * cinv;
                F3 cr3 = cross3(r, ce3);
                v2 = dot3(ce1, cr3) * cinv;
                F3 c2r = cross3(ce2, r);
                v3 = dot3(ce1, c2r) * cinv;
                v0 = 1.0f - (v1 + v2 + v3);
                ins = (v0 >= -1e-6f) && (v1 >= -1e-6f) &&
                      (v2 >= -1e-6f) && (v3 >= -1e-6f);
            }
            bool valid = alive && ins;

            if (lane == 0) {
                int idx = ray * MAXS + k;
                if (valid) {
                    o_ray[idx] = (float)ray;
                    o_tet[idx] = (float)tet;
                    ((float4*)o_bar)[idx] = make_float4(v0, v1, v2, v3);
                    o_pos[3 * idx + 0] = pw.x;
                    o_pos[3 * idx + 1] = pw.y;
                    o_pos[3 * idx + 2] = pw.z;
                } else {
                    o_ray[idx] = -1.0f;
                    o_tet[idx] = -1.0f;
                    ((float4*)o_bar)[idx] = make_float4(0.f, 0.f, 0.f, 0.f);
                    o_pos[3 * idx + 0] = 0.0f;
                    o_pos[3 * idx + 1] = 0.0f;
                    o_pos[3 * idx + 2] = 0.0f;
                }
            }
            k += 1;
        }
    }
}

// ---------------- launch ------------------------------------------------------
extern "C" void kernel_launch(void* const* d_in, const int* in_sizes, int n_in,
                              void* d_out, int out_size) {
    const float* cage   = (const float*)d_in[0];  // (1, 729, 3) f32
    const float* ro     = (const float*)d_in[1];  // (1, 4096, 3) f32
    const float* rd     = (const float*)d_in[2];  // (1, 4096, 3) f32
    const int*   tetras = (const int*)d_in[3];    // (3072, 4) i32
    const int*   faces  = (const int*)d_in[4];    // (3072, 4, 3) i32
    const int*   topo   = (const int*)d_in[5];    // (3072, 4) i32
    float* out = (float*)d_out;

    cudaFuncSetAttribute(k_all, cudaFuncAttributeMaxDynamicSharedMemorySize,
                         SMEM_TOTAL);
    k_all<<<NRAYS / 32, 1024, SMEM_TOTAL>>>(cage, ro, rd, tetras, faces, topo, out);
}